// round 1
// baseline (speedup 1.0000x reference)
#include <cuda_runtime.h>
#include <math.h>
#include <stdint.h>

#define HH 100
#define WW 100
#define NPIX 10000
#define CC 1024
#define AA 9
#define NANCH 90000          // 100*100*9
#define NDELT 360000         // 100*100*36
#define PRE 6000
#define POST 300
#define NSORT 131072         // next pow2 >= 90000
#define NWORDS 188           // ceil(6000/32)

// ---------------- device scratch (static, allowed) ----------------
__device__ float g_y[CC * NPIX];                 // conv1 output, [oc][pix]
__device__ float g_wT[9 * CC * CC];              // w1 transposed [tap][ic][oc]
__device__ unsigned long long g_keys[NSORT];     // (score_bits<<32)|idx
__device__ float g_boxes[PRE * 4];
__device__ float g_areas[PRE];
__device__ int   g_valid[PRE];
__device__ unsigned g_supp[PRE * NWORDS];

// ---------------- weight reorder: w1[oc][ic][tap] -> wT[tap][ic][oc] ----------------
__global__ void reorder_w(const float* __restrict__ w1) {
    int tid = blockIdx.x * 256 + threadIdx.x;
    if (tid >= 9 * CC * CC) return;
    int oc  = tid & (CC - 1);
    int ic  = (tid >> 10) & (CC - 1);
    int tap = tid >> 20;
    g_wT[tid] = w1[(oc * CC + ic) * 9 + tap];
}

// ---------------- 3x3 conv + bias + relu (fp32 SGEMM-style, tap-outer) ----------------
__global__ void __launch_bounds__(256) conv3x3_relu(const float* __restrict__ in,
                                                    const float* __restrict__ bias) {
    __shared__ __align__(16) float As[8][64];   // [kc][oc]
    __shared__ __align__(16) float Bs[8][68];   // [kc][px] (padded row)
    const int t  = threadIdx.x;
    const int tx = t & 15;
    const int ty = t >> 4;
    const int p0  = blockIdx.x * 64;
    const int oc0 = blockIdx.y * 64;

    float acc[4][4];
#pragma unroll
    for (int i = 0; i < 4; i++)
#pragma unroll
        for (int j = 0; j < 4; j++) acc[i][j] = 0.f;

    int kcL[2], ocL[2], pxL[2], pyL[2], pxxL[2];
    bool pvL[2];
#pragma unroll
    for (int l = 0; l < 2; l++) {
        int e = t + l * 256;
        kcL[l] = e >> 6;
        ocL[l] = e & 63;
        pxL[l] = e & 63;
        int p = p0 + pxL[l];
        pvL[l] = (p < NPIX);
        int pc = p < NPIX ? p : 0;
        pyL[l]  = pc / 100;
        pxxL[l] = pc % 100;
    }

    for (int tap = 0; tap < 9; ++tap) {
        const int dy = tap / 3 - 1, dx = tap % 3 - 1;
        const float* wtap = g_wT + tap * (CC * CC);
        int offL[2]; bool inbL[2];
#pragma unroll
        for (int l = 0; l < 2; l++) {
            int gy = pyL[l] + dy, gx = pxxL[l] + dx;
            inbL[l] = pvL[l] && ((unsigned)gy < 100u) && ((unsigned)gx < 100u);
            offL[l] = gy * 100 + gx;
        }
        for (int icc = 0; icc < CC; icc += 8) {
#pragma unroll
            for (int l = 0; l < 2; l++) {
                As[kcL[l]][ocL[l]] = wtap[(icc + kcL[l]) * CC + oc0 + ocL[l]];
                float v = 0.f;
                if (inbL[l]) v = in[(icc + kcL[l]) * NPIX + offL[l]];
                Bs[kcL[l]][pxL[l]] = v;
            }
            __syncthreads();
#pragma unroll
            for (int kc = 0; kc < 8; kc++) {
                float4 a4 = reinterpret_cast<float4*>(As[kc])[ty];
                float4 b4 = reinterpret_cast<float4*>(Bs[kc])[tx];
                float av[4] = {a4.x, a4.y, a4.z, a4.w};
                float bv[4] = {b4.x, b4.y, b4.z, b4.w};
#pragma unroll
                for (int i = 0; i < 4; i++)
#pragma unroll
                    for (int j = 0; j < 4; j++) acc[i][j] += av[i] * bv[j];
            }
            __syncthreads();
        }
    }
#pragma unroll
    for (int i = 0; i < 4; i++) {
        int oc = oc0 + ty * 4 + i;
        float b = bias[oc];
#pragma unroll
        for (int j = 0; j < 4; j++) {
            int p = p0 + tx * 4 + j;
            if (p < NPIX) g_y[oc * NPIX + p] = fmaxf(acc[i][j] + b, 0.f);
        }
    }
}

// ---------------- 1x1 heads: sigmoid scores + deltas; emit sort keys ----------------
__global__ void __launch_bounds__(128) heads_kernel(const float* __restrict__ wc,
                                                    const float* __restrict__ bc,
                                                    const float* __restrict__ wb,
                                                    const float* __restrict__ bb,
                                                    float* __restrict__ out) {
    __shared__ __align__(16) float ws[64][48];
    const int t = threadIdx.x;
    const int p = blockIdx.x * 128 + t;
    const bool act = p < NPIX;
    float acc[48];
#pragma unroll
    for (int o = 0; o < 48; o++) acc[o] = 0.f;

    for (int icc = 0; icc < CC; icc += 64) {
        for (int e = t; e < 64 * 48; e += 128) {
            int ic = e / 48, o = e - ic * 48;
            float w = 0.f;
            if (o < 9)       w = wc[o * CC + icc + ic];
            else if (o < 45) w = wb[(o - 9) * CC + icc + ic];
            ws[ic][o] = w;
        }
        __syncthreads();
        if (act) {
            for (int ic = 0; ic < 64; ++ic) {
                float v = g_y[(icc + ic) * NPIX + p];
#pragma unroll
                for (int o4 = 0; o4 < 12; o4++) {
                    float4 w4 = reinterpret_cast<float4*>(ws[ic])[o4];
                    acc[o4 * 4 + 0] += w4.x * v;
                    acc[o4 * 4 + 1] += w4.y * v;
                    acc[o4 * 4 + 2] += w4.z * v;
                    acc[o4 * 4 + 3] += w4.w * v;
                }
            }
        }
        __syncthreads();
    }
    if (act) {
#pragma unroll
        for (int a = 0; a < 9; ++a) {
            float z = acc[a] + bc[a];
            float s = 1.f / (1.f + expf(-z));
            out[p * 9 + a] = s;
            g_keys[p * 9 + a] =
                ((unsigned long long)__float_as_uint(s) << 32) | (unsigned)(p * 9 + a);
        }
#pragma unroll
        for (int c = 0; c < 36; ++c)
            out[NANCH + p * 36 + c] = acc[9 + c] + bb[c];
    }
}

__global__ void pad_keys() {
    int i = NANCH + blockIdx.x * 256 + threadIdx.x;
    if (i < NSORT) g_keys[i] = 0ULL;
}

// ---------------- bitonic sort (descending) on u64 keys ----------------
__global__ void __launch_bounds__(1024) bsort_local() {
    __shared__ unsigned long long s[2048];
    const int t = threadIdx.x;
    const int base = blockIdx.x * 2048;
    s[t] = g_keys[base + t];
    s[t + 1024] = g_keys[base + t + 1024];
    __syncthreads();
    for (int k = 2; k <= 2048; k <<= 1) {
        for (int j = k >> 1; j > 0; j >>= 1) {
#pragma unroll
            for (int l = 0; l < 2; l++) {
                int i = t + l * 1024;
                int ixj = i ^ j;
                if (ixj > i) {
                    unsigned long long a = s[i], b = s[ixj];
                    bool desc = (((base + i) & k) == 0);
                    if (desc ? (a < b) : (a > b)) { s[i] = b; s[ixj] = a; }
                }
            }
            __syncthreads();
        }
    }
    g_keys[base + t] = s[t];
    g_keys[base + t + 1024] = s[t + 1024];
}

__global__ void __launch_bounds__(1024) bsort_merge(int k) {
    __shared__ unsigned long long s[2048];
    const int t = threadIdx.x;
    const int base = blockIdx.x * 2048;
    s[t] = g_keys[base + t];
    s[t + 1024] = g_keys[base + t + 1024];
    __syncthreads();
    for (int j = 1024; j > 0; j >>= 1) {
#pragma unroll
        for (int l = 0; l < 2; l++) {
            int i = t + l * 1024;
            int ixj = i ^ j;
            if (ixj > i) {
                unsigned long long a = s[i], b = s[ixj];
                bool desc = (((base + i) & k) == 0);
                if (desc ? (a < b) : (a > b)) { s[i] = b; s[ixj] = a; }
            }
        }
        __syncthreads();
    }
    g_keys[base + t] = s[t];
    g_keys[base + t + 1024] = s[t + 1024];
}

__global__ void bsort_global(int k, int j) {
    int i = blockIdx.x * 256 + threadIdx.x;
    int ixj = i ^ j;
    if (ixj > i && ixj < NSORT) {
        unsigned long long a = g_keys[i], b = g_keys[ixj];
        bool desc = ((i & k) == 0);
        if (desc ? (a < b) : (a > b)) { g_keys[i] = b; g_keys[ixj] = a; }
    }
}

// ---------------- decode top-6000 proposals + clip + min-size ----------------
__global__ void decode_kernel(const float* __restrict__ amap,
                              const float* __restrict__ out,
                              const int* __restrict__ ishape) {
    int i = blockIdx.x * 256 + threadIdx.x;
    if (i >= PRE) return;
    unsigned idx = (unsigned)(g_keys[i] & 0xffffffffULL);
    int a = idx % 9u;
    int p = idx / 9u;
    const float* an = amap + p * 36 + a * 4;
    float acy = an[0], acx = an[1], ah = an[2], aw = an[3];
    const float* dl = out + NANCH + p * 36 + a * 4;
    float ddy = dl[0], ddx = dl[1], ddh = dl[2], ddw = dl[3];
    float cy = acy + ddy * ah;
    float cx = acx + ddx * aw;
    float sh = ah * expf(ddh);
    float sw = aw * expf(ddw);
    float y1 = cy - 0.5f * sh;
    float x1 = cx - 0.5f * sw;
    float y2 = cy + 0.5f * sh;
    float x2 = cx + 0.5f * sw;
    y1 = fmaxf(y1, 0.f);
    x1 = fmaxf(x1, 0.f);
    y2 = fminf(y2, (float)ishape[1]);
    x2 = fminf(x2, (float)ishape[2]);
    float hh = y2 - y1, wd = x2 - x1;
    g_boxes[i * 4 + 0] = y1;
    g_boxes[i * 4 + 1] = x1;
    g_boxes[i * 4 + 2] = y2;
    g_boxes[i * 4 + 3] = x2;
    g_areas[i] = hh * wd;
    g_valid[i] = (hh >= 16.f) && (wd >= 16.f);
}

// ---------------- pairwise suppression bitmask ----------------
__global__ void supp_kernel() {
    int tid = blockIdx.x * 256 + threadIdx.x;
    if (tid >= PRE * NWORDS) return;
    int i = tid / NWORDS;
    int jw = tid - i * NWORDS;
    float y1i = g_boxes[i * 4 + 0], x1i = g_boxes[i * 4 + 1];
    float y2i = g_boxes[i * 4 + 2], x2i = g_boxes[i * 4 + 3];
    float ai = g_areas[i];
    unsigned m = 0;
    int jb = jw * 32;
    for (int b = 0; b < 32; ++b) {
        int j = jb + b;
        if (j < PRE && j > i) {
            float iy1 = fmaxf(y1i, g_boxes[j * 4 + 0]);
            float ix1 = fmaxf(x1i, g_boxes[j * 4 + 1]);
            float iy2 = fminf(y2i, g_boxes[j * 4 + 2]);
            float ix2 = fminf(x2i, g_boxes[j * 4 + 3]);
            float inter = fmaxf(iy2 - iy1, 0.f) * fmaxf(ix2 - ix1, 0.f);
            float iou = inter / (ai + g_areas[j] - inter + 1e-8f);
            if (iou > 0.7f) m |= (1u << b);
        }
    }
    g_supp[tid] = m;
}

// ---------------- sequential NMS collect (single warp), early exit @300 ----------------
__global__ void collect_kernel(float* __restrict__ out) {
    __shared__ unsigned rm[NWORDS];
    __shared__ int pos[POST];
    const int lane = threadIdx.x;
    for (int w = lane; w < NWORDS; w += 32) {
        unsigned m = 0;
#pragma unroll
        for (int b = 0; b < 32; ++b) {
            int idx = w * 32 + b;
            bool bad = (idx >= PRE) || (g_valid[idx] == 0);
            if (bad) m |= (1u << b);
        }
        rm[w] = m;
    }
    __syncwarp();
    int cnt = 0;
    for (int i = 0; i < PRE && cnt < POST; ++i) {
        unsigned word = rm[i >> 5];
        if (word & (1u << (i & 31))) continue;
        if (lane == 0) pos[cnt] = i;
        cnt++;
        const unsigned* row = g_supp + i * NWORDS;
        for (int w = lane; w < NWORDS; w += 32) rm[w] |= row[w];
        __syncwarp();
    }
    __syncwarp();
    for (int k = lane; k < POST; k += 32) {
        float4 bx = make_float4(0.f, 0.f, 0.f, 0.f);
        if (k < cnt) {
            int p = pos[k];
            bx = *reinterpret_cast<float4*>(&g_boxes[p * 4]);
        }
        reinterpret_cast<float4*>(out + NANCH + NDELT)[k] = bx;
    }
}

// ---------------- launch ----------------
extern "C" void kernel_launch(void* const* d_in, const int* in_sizes, int n_in,
                              void* d_out, int out_size) {
    auto find = [&](long long sz) -> int {
        for (int i = 0; i < n_in; ++i)
            if ((long long)in_sizes[i] == sz) return i;
        return 0;
    };
    const float* feat  = (const float*)d_in[find(10240000)];
    const int*   ishp  = (const int*)  d_in[find(3)];
    const float* amap  = (const float*)d_in[find(360000)];
    const float* w1    = (const float*)d_in[find(9437184)];
    const float* b1    = (const float*)d_in[find(1024)];
    const float* wcls  = (const float*)d_in[find(9216)];
    const float* bcls  = (const float*)d_in[find(9)];
    const float* wbox  = (const float*)d_in[find(36864)];
    const float* bbox  = (const float*)d_in[find(36)];
    float* out = (float*)d_out;

    reorder_w<<<(9 * CC * CC + 255) / 256, 256>>>(w1);
    conv3x3_relu<<<dim3((NPIX + 63) / 64, CC / 64), 256>>>(feat, b1);
    heads_kernel<<<(NPIX + 127) / 128, 128>>>(wcls, bcls, wbox, bbox, out);
    pad_keys<<<(NSORT - NANCH + 255) / 256, 256>>>();

    bsort_local<<<NSORT / 2048, 1024>>>();
    for (int k = 4096; k <= NSORT; k <<= 1) {
        for (int j = k >> 1; j >= 2048; j >>= 1)
            bsort_global<<<NSORT / 256, 256>>>(k, j);
        bsort_merge<<<NSORT / 2048, 1024>>>(k);
    }

    decode_kernel<<<(PRE + 255) / 256, 256>>>(amap, out, ishp);
    supp_kernel<<<(PRE * NWORDS + 255) / 256, 256>>>();
    collect_kernel<<<1, 32>>>(out);
}

// round 3
// speedup vs baseline: 2.2970x; 2.2970x over previous
#include <cuda_runtime.h>
#include <math.h>
#include <stdint.h>

#define HH 100
#define WW 100
#define NPIX 10000
#define CC 1024
#define AA 9
#define NANCH 90000
#define NDELT 360000
#define PRE 6000
#define POST 300
#define NSORT 131072
#define NWORDS 188
#define NT 640            // padded tile count (25*25=625 -> 640)
#define NTILE 625

// ---------------- device scratch ----------------
__device__ float g_y[CC * NPIX];                       // conv1 output [oc][pix]
__device__ float g_U[36 * CC * CC];                    // winograd filters [t][ic][oc]
__device__ float g_V[36 * CC * NT];                    // winograd inputs  [t][ic][tile]
__device__ float g_M[36 * CC * NT];                    // winograd products [t][oc][tile]
__device__ unsigned long long g_keys[NSORT];
__device__ float g_boxes[PRE * 4];
__device__ float g_areas[PRE];
__device__ int   g_valid[PRE];
__device__ unsigned g_supp[PRE * NWORDS];

// ---------------- winograd filter transform: U = G g G^T ----------------
__global__ void wino_filter(const float* __restrict__ w1) {
    int tid = blockIdx.x * 256 + threadIdx.x;     // 1,048,576
    int ic = tid >> 10, oc = tid & 1023;
    const float* g = w1 + ((size_t)oc * CC + ic) * 9;
    float gg[9];
#pragma unroll
    for (int k = 0; k < 9; ++k) gg[k] = g[k];
    const float c6 = 1.f / 6.f, c24 = 1.f / 24.f;
    float tmp[6][3];
#pragma unroll
    for (int j = 0; j < 3; ++j) {
        float g0 = gg[0 * 3 + j], g1 = gg[1 * 3 + j], g2 = gg[2 * 3 + j];
        tmp[0][j] = 0.25f * g0;
        tmp[1][j] = (-g0 - g1 - g2) * c6;
        tmp[2][j] = (-g0 + g1 - g2) * c6;
        tmp[3][j] = (g0 + 2.f * g1 + 4.f * g2) * c24;
        tmp[4][j] = (g0 - 2.f * g1 + 4.f * g2) * c24;
        tmp[5][j] = g2;
    }
    float* dst = g_U + (size_t)ic * 1024 + oc;
#pragma unroll
    for (int r = 0; r < 6; ++r) {
        float t0 = tmp[r][0], t1 = tmp[r][1], t2 = tmp[r][2];
        float u[6];
        u[0] = 0.25f * t0;
        u[1] = (-t0 - t1 - t2) * c6;
        u[2] = (-t0 + t1 - t2) * c6;
        u[3] = (t0 + 2.f * t1 + 4.f * t2) * c24;
        u[4] = (t0 - 2.f * t1 + 4.f * t2) * c24;
        u[5] = t2;
#pragma unroll
        for (int c = 0; c < 6; ++c)
            dst[(size_t)(r * 6 + c) * (CC * CC)] = u[c];
    }
}

// ---------------- winograd input transform: V = B^T d B ----------------
__global__ void __launch_bounds__(256) wino_input(const float* __restrict__ feat) {
    __shared__ float s[16][6][104];
    const int tyb = blockIdx.x;        // tile row 0..24
    const int icc = blockIdx.y * 16;   // ic chunk
    const int t = threadIdx.x;
    const int r0 = tyb * 4 - 1;

    for (int r = 0; r < 6; ++r) {
        int gr = r0 + r;
        bool vr = (unsigned)gr < 100u;
        const float* src = feat + (size_t)icc * NPIX + gr * 100;
        for (int e = t; e < 1600; e += 256) {
            int ic = e / 100, col = e - ic * 100;
            s[ic][r][col] = vr ? src[(size_t)ic * NPIX + col] : 0.f;
        }
    }
    __syncthreads();

    for (int q = t; q < 400; q += 256) {
        int ic = q / 25, tx = q - (q / 25) * 25;
        int c0 = tx * 4 - 1;
        float w[6][6];
#pragma unroll
        for (int c = 0; c < 6; ++c) {
            int col = c0 + c;
            bool vc = (unsigned)col < 100u;
            float d0 = vc ? s[ic][0][col] : 0.f;
            float d1 = vc ? s[ic][1][col] : 0.f;
            float d2 = vc ? s[ic][2][col] : 0.f;
            float d3 = vc ? s[ic][3][col] : 0.f;
            float d4 = vc ? s[ic][4][col] : 0.f;
            float d5 = vc ? s[ic][5][col] : 0.f;
            w[0][c] = 4.f * d0 - 5.f * d2 + d4;
            w[1][c] = -4.f * d1 - 4.f * d2 + d3 + d4;
            w[2][c] = 4.f * d1 - 4.f * d2 - d3 + d4;
            w[3][c] = -2.f * d1 - d2 + 2.f * d3 + d4;
            w[4][c] = 2.f * d1 - d2 - 2.f * d3 + d4;
            w[5][c] = 4.f * d1 - 5.f * d3 + d5;
        }
        float* dst = g_V + (size_t)(icc + ic) * NT + (tyb * 25 + tx);
#pragma unroll
        for (int i = 0; i < 6; ++i) {
            float w0 = w[i][0], w1 = w[i][1], w2 = w[i][2];
            float w3 = w[i][3], w4 = w[i][4], w5 = w[i][5];
            float v[6];
            v[0] = 4.f * w0 - 5.f * w2 + w4;
            v[1] = -4.f * w1 - 4.f * w2 + w3 + w4;
            v[2] = 4.f * w1 - 4.f * w2 - w3 + w4;
            v[3] = -2.f * w1 - w2 + 2.f * w3 + w4;
            v[4] = 2.f * w1 - w2 - 2.f * w3 + w4;
            v[5] = 4.f * w1 - 5.f * w3 + w5;
#pragma unroll
            for (int j = 0; j < 6; ++j)
                dst[(size_t)(i * 6 + j) * (CC * NT)] = v[j];
        }
    }
}

// ---------------- 36 batched GEMMs: M_t = U_t * V_t  (M=1024,N=640,K=1024) ----------------
__global__ void __launch_bounds__(256) wino_gemm() {
    __shared__ __align__(16) float As[8][64];
    __shared__ __align__(16) float Bs[8][68];
    const int t = threadIdx.x;
    const int tx = t & 15;
    const int ty = t >> 4;
    const int n0 = blockIdx.x * 64;
    const int oc0 = blockIdx.y * 64;
    const int z = blockIdx.z;
    const float* A = g_U + (size_t)z * (CC * CC);
    const float* B = g_V + (size_t)z * (CC * NT);
    float* Mo = g_M + (size_t)z * (CC * NT);

    float acc[4][4];
#pragma unroll
    for (int i = 0; i < 4; i++)
#pragma unroll
        for (int j = 0; j < 4; j++) acc[i][j] = 0.f;

    int kcL[2], colL[2];
#pragma unroll
    for (int l = 0; l < 2; l++) {
        int e = t + l * 256;
        kcL[l] = e >> 6;
        colL[l] = e & 63;
    }

    for (int icc = 0; icc < CC; icc += 8) {
#pragma unroll
        for (int l = 0; l < 2; l++) {
            As[kcL[l]][colL[l]] = A[(size_t)(icc + kcL[l]) * CC + oc0 + colL[l]];
            Bs[kcL[l]][colL[l]] = B[(size_t)(icc + kcL[l]) * NT + n0 + colL[l]];
        }
        __syncthreads();
#pragma unroll
        for (int kc = 0; kc < 8; kc++) {
            float4 a4 = reinterpret_cast<float4*>(As[kc])[ty];
            float4 b4 = reinterpret_cast<float4*>(Bs[kc])[tx];
            float av[4] = {a4.x, a4.y, a4.z, a4.w};
            float bv[4] = {b4.x, b4.y, b4.z, b4.w};
#pragma unroll
            for (int i = 0; i < 4; i++)
#pragma unroll
                for (int j = 0; j < 4; j++) acc[i][j] += av[i] * bv[j];
        }
        __syncthreads();
    }
#pragma unroll
    for (int i = 0; i < 4; i++) {
        float4 o = make_float4(acc[i][0], acc[i][1], acc[i][2], acc[i][3]);
        *reinterpret_cast<float4*>(Mo + (size_t)(oc0 + ty * 4 + i) * NT + n0 + tx * 4) = o;
    }
}

// ---------------- winograd output transform: y = A^T m A + bias, relu ----------------
__global__ void __launch_bounds__(256) wino_output(const float* __restrict__ bias) {
    const int oc = blockIdx.x;
    const float b = bias[oc];
    float* ybase = g_y + (size_t)oc * NPIX;
    const float* msrc = g_M + (size_t)oc * NT;
    for (int tile = threadIdx.x; tile < NTILE; tile += 256) {
        int ty = tile / 25, tx = tile - ty * 25;
        float m[36];
#pragma unroll
        for (int k = 0; k < 36; ++k)
            m[k] = msrc[(size_t)k * (CC * NT) + tile];
        float w[4][6];
#pragma unroll
        for (int c = 0; c < 6; ++c) {
            float m0 = m[0 * 6 + c], m1 = m[1 * 6 + c], m2 = m[2 * 6 + c];
            float m3 = m[3 * 6 + c], m4 = m[4 * 6 + c], m5 = m[5 * 6 + c];
            w[0][c] = m0 + m1 + m2 + m3 + m4;
            w[1][c] = m1 - m2 + 2.f * m3 - 2.f * m4;
            w[2][c] = m1 + m2 + 4.f * m3 + 4.f * m4;
            w[3][c] = m1 - m2 + 8.f * m3 - 8.f * m4 + m5;
        }
#pragma unroll
        for (int i = 0; i < 4; ++i) {
            float w0 = w[i][0], w1 = w[i][1], w2 = w[i][2];
            float w3 = w[i][3], w4 = w[i][4], w5 = w[i][5];
            float o0 = w0 + w1 + w2 + w3 + w4;
            float o1 = w1 - w2 + 2.f * w3 - 2.f * w4;
            float o2 = w1 + w2 + 4.f * w3 + 4.f * w4;
            float o3 = w1 - w2 + 8.f * w3 - 8.f * w4 + w5;
            float4 o = make_float4(fmaxf(o0 + b, 0.f), fmaxf(o1 + b, 0.f),
                                   fmaxf(o2 + b, 0.f), fmaxf(o3 + b, 0.f));
            *reinterpret_cast<float4*>(ybase + (ty * 4 + i) * 100 + tx * 4) = o;
        }
    }
}

// ---------------- 1x1 heads: sigmoid scores + deltas; emit sort keys ----------------
__global__ void __launch_bounds__(128) heads_kernel(const float* __restrict__ wc,
                                                    const float* __restrict__ bc,
                                                    const float* __restrict__ wb,
                                                    const float* __restrict__ bb,
                                                    float* __restrict__ out) {
    __shared__ __align__(16) float ws[64][48];
    const int t = threadIdx.x;
    const int p = blockIdx.x * 128 + t;
    const bool act = p < NPIX;
    float acc[48];
#pragma unroll
    for (int o = 0; o < 48; o++) acc[o] = 0.f;

    for (int icc = 0; icc < CC; icc += 64) {
        for (int e = t; e < 64 * 48; e += 128) {
            int ic = e / 48, o = e - ic * 48;
            float w = 0.f;
            if (o < 9)       w = wc[o * CC + icc + ic];
            else if (o < 45) w = wb[(o - 9) * CC + icc + ic];
            ws[ic][o] = w;
        }
        __syncthreads();
        if (act) {
            for (int ic = 0; ic < 64; ++ic) {
                float v = g_y[(size_t)(icc + ic) * NPIX + p];
#pragma unroll
                for (int o4 = 0; o4 < 12; o4++) {
                    float4 w4 = reinterpret_cast<float4*>(ws[ic])[o4];
                    acc[o4 * 4 + 0] += w4.x * v;
                    acc[o4 * 4 + 1] += w4.y * v;
                    acc[o4 * 4 + 2] += w4.z * v;
                    acc[o4 * 4 + 3] += w4.w * v;
                }
            }
        }
        __syncthreads();
    }
    if (act) {
#pragma unroll
        for (int a = 0; a < 9; ++a) {
            float z = acc[a] + bc[a];
            float s = 1.f / (1.f + expf(-z));
            out[p * 9 + a] = s;
            g_keys[p * 9 + a] =
                ((unsigned long long)__float_as_uint(s) << 32) | (unsigned)(p * 9 + a);
        }
#pragma unroll
        for (int c = 0; c < 36; ++c)
            out[NANCH + p * 36 + c] = acc[9 + c] + bb[c];
    }
}

__global__ void pad_keys() {
    int i = NANCH + blockIdx.x * 256 + threadIdx.x;
    if (i < NSORT) g_keys[i] = 0ULL;
}

// ---------------- bitonic sort (descending) on u64 keys ----------------
__global__ void __launch_bounds__(1024) bsort_local() {
    __shared__ unsigned long long s[2048];
    const int t = threadIdx.x;
    const int base = blockIdx.x * 2048;
    s[t] = g_keys[base + t];
    s[t + 1024] = g_keys[base + t + 1024];
    __syncthreads();
    for (int k = 2; k <= 2048; k <<= 1) {
        for (int j = k >> 1; j > 0; j >>= 1) {
#pragma unroll
            for (int l = 0; l < 2; l++) {
                int i = t + l * 1024;
                int ixj = i ^ j;
                if (ixj > i) {
                    unsigned long long a = s[i], b = s[ixj];
                    bool desc = (((base + i) & k) == 0);
                    if (desc ? (a < b) : (a > b)) { s[i] = b; s[ixj] = a; }
                }
            }
            __syncthreads();
        }
    }
    g_keys[base + t] = s[t];
    g_keys[base + t + 1024] = s[t + 1024];
}

__global__ void __launch_bounds__(1024) bsort_merge(int k) {
    __shared__ unsigned long long s[2048];
    const int t = threadIdx.x;
    const int base = blockIdx.x * 2048;
    s[t] = g_keys[base + t];
    s[t + 1024] = g_keys[base + t + 1024];
    __syncthreads();
    for (int j = 1024; j > 0; j >>= 1) {
#pragma unroll
        for (int l = 0; l < 2; l++) {
            int i = t + l * 1024;
            int ixj = i ^ j;
            if (ixj > i) {
                unsigned long long a = s[i], b = s[ixj];
                bool desc = (((base + i) & k) == 0);
                if (desc ? (a < b) : (a > b)) { s[i] = b; s[ixj] = a; }
            }
        }
        __syncthreads();
    }
    g_keys[base + t] = s[t];
    g_keys[base + t + 1024] = s[t + 1024];
}

__global__ void bsort_global(int k, int j) {
    int i = blockIdx.x * 256 + threadIdx.x;
    int ixj = i ^ j;
    if (ixj > i && ixj < NSORT) {
        unsigned long long a = g_keys[i], b = g_keys[ixj];
        bool desc = ((i & k) == 0);
        if (desc ? (a < b) : (a > b)) { g_keys[i] = b; g_keys[ixj] = a; }
    }
}

// ---------------- decode top-6000 proposals + clip + min-size ----------------
__global__ void decode_kernel(const float* __restrict__ amap,
                              const float* __restrict__ out,
                              const int* __restrict__ ishape) {
    int i = blockIdx.x * 256 + threadIdx.x;
    if (i >= PRE) return;
    unsigned idx = (unsigned)(g_keys[i] & 0xffffffffULL);
    int a = idx % 9u;
    int p = idx / 9u;
    const float* an = amap + p * 36 + a * 4;
    float acy = an[0], acx = an[1], ah = an[2], aw = an[3];
    const float* dl = out + NANCH + p * 36 + a * 4;
    float ddy = dl[0], ddx = dl[1], ddh = dl[2], ddw = dl[3];
    float cy = acy + ddy * ah;
    float cx = acx + ddx * aw;
    float sh = ah * expf(ddh);
    float sw = aw * expf(ddw);
    float y1 = fmaxf(cy - 0.5f * sh, 0.f);
    float x1 = fmaxf(cx - 0.5f * sw, 0.f);
    float y2 = fminf(cy + 0.5f * sh, (float)ishape[1]);
    float x2 = fminf(cx + 0.5f * sw, (float)ishape[2]);
    float hh = y2 - y1, wd = x2 - x1;
    g_boxes[i * 4 + 0] = y1;
    g_boxes[i * 4 + 1] = x1;
    g_boxes[i * 4 + 2] = y2;
    g_boxes[i * 4 + 3] = x2;
    g_areas[i] = hh * wd;
    g_valid[i] = (hh >= 16.f) && (wd >= 16.f);
}

// ---------------- pairwise suppression bitmask ----------------
__global__ void supp_kernel() {
    int tid = blockIdx.x * 256 + threadIdx.x;
    if (tid >= PRE * NWORDS) return;
    int i = tid / NWORDS;
    int jw = tid - i * NWORDS;
    float y1i = g_boxes[i * 4 + 0], x1i = g_boxes[i * 4 + 1];
    float y2i = g_boxes[i * 4 + 2], x2i = g_boxes[i * 4 + 3];
    float ai = g_areas[i];
    unsigned m = 0;
    int jb = jw * 32;
    for (int b = 0; b < 32; ++b) {
        int j = jb + b;
        if (j < PRE && j > i) {
            float iy1 = fmaxf(y1i, g_boxes[j * 4 + 0]);
            float ix1 = fmaxf(x1i, g_boxes[j * 4 + 1]);
            float iy2 = fminf(y2i, g_boxes[j * 4 + 2]);
            float ix2 = fminf(x2i, g_boxes[j * 4 + 3]);
            float inter = fmaxf(iy2 - iy1, 0.f) * fmaxf(ix2 - ix1, 0.f);
            float iou = inter / (ai + g_areas[j] - inter + 1e-8f);
            if (iou > 0.7f) m |= (1u << b);
        }
    }
    g_supp[tid] = m;
}

// ---------------- sequential NMS collect (single warp), early exit @300 ----------------
__global__ void collect_kernel(float* __restrict__ out) {
    __shared__ unsigned rm[NWORDS];
    __shared__ int pos[POST];
    const int lane = threadIdx.x;
    for (int w = lane; w < NWORDS; w += 32) {
        unsigned m = 0;
#pragma unroll
        for (int b = 0; b < 32; ++b) {
            int idx = w * 32 + b;
            bool bad = (idx >= PRE) || (g_valid[idx] == 0);
            if (bad) m |= (1u << b);
        }
        rm[w] = m;
    }
    __syncwarp();
    int cnt = 0;
    for (int i = 0; i < PRE && cnt < POST; ++i) {
        unsigned word = rm[i >> 5];
        if (word & (1u << (i & 31))) continue;
        if (lane == 0) pos[cnt] = i;
        cnt++;
        const unsigned* row = g_supp + i * NWORDS;
        for (int w = lane; w < NWORDS; w += 32) rm[w] |= row[w];
        __syncwarp();
    }
    __syncwarp();
    for (int k = lane; k < POST; k += 32) {
        float4 bx = make_float4(0.f, 0.f, 0.f, 0.f);
        if (k < cnt) {
            int p = pos[k];
            bx = *reinterpret_cast<float4*>(&g_boxes[p * 4]);
        }
        reinterpret_cast<float4*>(out + NANCH + NDELT)[k] = bx;
    }
}

// ---------------- launch ----------------
extern "C" void kernel_launch(void* const* d_in, const int* in_sizes, int n_in,
                              void* d_out, int out_size) {
    auto find = [&](long long sz) -> int {
        for (int i = 0; i < n_in; ++i)
            if ((long long)in_sizes[i] == sz) return i;
        return 0;
    };
    const float* feat  = (const float*)d_in[find(10240000)];
    const int*   ishp  = (const int*)  d_in[find(3)];
    const float* amap  = (const float*)d_in[find(360000)];
    const float* w1    = (const float*)d_in[find(9437184)];
    const float* b1    = (const float*)d_in[find(1024)];
    const float* wcls  = (const float*)d_in[find(9216)];
    const float* bcls  = (const float*)d_in[find(9)];
    const float* wbox  = (const float*)d_in[find(36864)];
    const float* bbox  = (const float*)d_in[find(36)];
    float* out = (float*)d_out;

    wino_filter<<<4096, 256>>>(w1);
    wino_input<<<dim3(25, 64), 256>>>(feat);
    wino_gemm<<<dim3(10, 16, 36), 256>>>();
    wino_output<<<1024, 256>>>(b1);

    heads_kernel<<<(NPIX + 127) / 128, 128>>>(wcls, bcls, wbox, bbox, out);
    pad_keys<<<(NSORT - NANCH + 255) / 256, 256>>>();

    bsort_local<<<NSORT / 2048, 1024>>>();
    for (int k = 4096; k <= NSORT; k <<= 1) {
        for (int j = k >> 1; j >= 2048; j >>= 1)
            bsort_global<<<NSORT / 256, 256>>>(k, j);
        bsort_merge<<<NSORT / 2048, 1024>>>(k);
    }

    decode_kernel<<<(PRE + 255) / 256, 256>>>(amap, out, ishp);
    supp_kernel<<<(PRE * NWORDS + 255) / 256, 256>>>();
    collect_kernel<<<1, 32>>>(out);
}